// round 14
// baseline (speedup 1.0000x reference)
#include <cuda_runtime.h>
#include <cuda_bf16.h>
#include <math.h>
#include <cstdint>

#define NTH 256

static __device__ __forceinline__ float seluf(float x) {
    const float lam    = 1.0507009873554805f;
    const float lamalp = 1.7580993408473766f;
    float e = __expf(x) - 1.0f;
    return x > 0.0f ? lam * x : lamalp * e;
}
static __device__ __forceinline__ float softplusf(float x) {
    return fmaxf(x, 0.0f) + log1pf(expf(-fabsf(x)));
}

static __device__ __forceinline__ void splitbf(float v, unsigned short& h, unsigned short& l) {
    __nv_bfloat16 hb = __float2bfloat16(v);
    float r = v - __bfloat162float(hb);
    __nv_bfloat16 lb = __float2bfloat16(r);
    h = __bfloat16_as_ushort(hb);
    l = __bfloat16_as_ushort(lb);
}
static __device__ __forceinline__ uint32_t pk16(unsigned short a, unsigned short b) {
    return (uint32_t)a | ((uint32_t)b << 16);
}

static __device__ __forceinline__ void mma_bf16(float d[4],
    uint32_t a0, uint32_t a1, uint32_t a2, uint32_t a3, uint32_t b0, uint32_t b1)
{
    asm volatile(
        "mma.sync.aligned.m16n8k16.row.col.f32.bf16.bf16.f32 "
        "{%0,%1,%2,%3}, {%4,%5,%6,%7}, {%8,%9}, {%0,%1,%2,%3};\n"
        : "+f"(d[0]), "+f"(d[1]), "+f"(d[2]), "+f"(d[3])
        : "r"(a0), "r"(a1), "r"(a2), "r"(a3), "r"(b0), "r"(b1));
}

// SMEM layout (bytes)
// W1 tiles: 64 rows x 96B (24 words, w' = w ^ (j&4)); W2: 64x128B XOR-swizzled;
// W3: 16x128B XOR-swizzled.
#define OFF_W1H 0
#define OFF_W1L 6144
#define OFF_W2H 12288
#define OFF_W2L 20480
#define OFF_W3H 28672
#define OFF_W3L 30720
#define OFF_B1  32768
#define OFF_B2  33024
#define OFF_B3  33280
#define OFF_ENC 33344                  // 256 rows x 41 floats = 41,984 B
#define SMEM_SZ 75328

#define ENC_PITCH 41

__global__ void __launch_bounds__(NTH, 3)
fused_kernel(
    const float*  __restrict__ vertices,
    const int4*   __restrict__ indices,
    const float*  __restrict__ camera,
    const float4* __restrict__ tables4,
    const float*  __restrict__ W1, const float* __restrict__ B1,
    const float*  __restrict__ W2, const float* __restrict__ B2,
    const float*  __restrict__ W3, const float* __restrict__ B3,
    const float*  __restrict__ centerp,
    const float*  __restrict__ scalep,
    float*        __restrict__ outp,
    int T)
{
    extern __shared__ __align__(16) unsigned char sm[];
    const int tid  = threadIdx.x;
    const int lane = tid & 31;
    const int warp = tid >> 5;
    const int g    = lane >> 2;
    const int q    = lane & 3;
    const int gx   = g << 4;           // XOR mask for W2/W3 (128B rows)
    const int g4   = g & 4;            // XOR mask for W1 (96B rows)

    // ---- zero W1 region (covers k pairs 20..23 padding) ----
    for (int i = tid; i < 12288 / 4; i += NTH) ((uint32_t*)sm)[i] = 0;
    __syncthreads();

    // ---- stage weights: pairs of k per u32 word ----
    for (int p = tid; p < 20 * 64; p += NTH) {           // W1: 96B rows, w' = w ^ (j&4)
        int j = p & 63, i0 = (p >> 6) << 1;
        unsigned short h0, l0, h1, l1;
        splitbf(W1[i0 * 64 + j],      h0, l0);
        splitbf(W1[i0 * 64 + 64 + j], h1, l1);
        int w = i0 >> 1;
        int byte = j * 96 + (((w ^ (j & 4)) << 2));
        *(uint32_t*)(sm + OFF_W1H + byte) = pk16(h0, h1);
        *(uint32_t*)(sm + OFF_W1L + byte) = pk16(l0, l1);
    }
    for (int p = tid; p < 32 * 64; p += NTH) {           // W2: 128B rows, XOR swizzle
        int j = p & 63, i0 = (p >> 6) << 1;
        unsigned short h0, l0, h1, l1;
        splitbf(W2[i0 * 64 + j],      h0, l0);
        splitbf(W2[i0 * 64 + 64 + j], h1, l1);
        int w = i0 >> 1;
        int byte = j * 128 + (((w << 2) ^ ((j & 7) << 4)));
        *(uint32_t*)(sm + OFF_W2H + byte) = pk16(h0, h1);
        *(uint32_t*)(sm + OFF_W2L + byte) = pk16(l0, l1);
    }
    for (int p = tid; p < 32 * 16; p += NTH) {           // W3
        int j = p & 15, i0 = (p >> 4) << 1;
        unsigned short h0, l0, h1, l1;
        splitbf(W3[i0 * 16 + j],      h0, l0);
        splitbf(W3[i0 * 16 + 16 + j], h1, l1);
        int w = i0 >> 1;
        int byte = j * 128 + (((w << 2) ^ ((j & 7) << 4)));
        *(uint32_t*)(sm + OFF_W3H + byte) = pk16(h0, h1);
        *(uint32_t*)(sm + OFF_W3L + byte) = pk16(l0, l1);
    }
    if (tid < 64) {
        ((float*)(sm + OFF_B1))[tid] = B1[tid];
        ((float*)(sm + OFF_B2))[tid] = B2[tid];
    }
    if (tid < 16) ((float*)(sm + OFF_B3))[tid] = B3[tid];
    __syncthreads();

    const float* b1s = (const float*)(sm + OFF_B1);
    const float* b2s = (const float*)(sm + OFF_B2);
    const float* b3s = (const float*)(sm + OFF_B3);
    float* senc = (float*)(sm + OFF_ENC);

    const int t0 = blockIdx.x * NTH;
    const float EPSF = 1.1920928955078125e-07f;

    // ================= enc phase (thread = tet t0+tid, row tid) =================
    float vdx, vdy, vdz;
    {
        int t = t0 + tid;
        int tc = (t < T) ? t : (T - 1);

        int4 id = indices[tc];
        float v0x = __ldg(vertices + 3 * id.x + 0);
        float v0y = __ldg(vertices + 3 * id.x + 1);
        float v0z = __ldg(vertices + 3 * id.x + 2);
        float v1x = __ldg(vertices + 3 * id.y + 0);
        float v1y = __ldg(vertices + 3 * id.y + 1);
        float v1z = __ldg(vertices + 3 * id.y + 2);
        float v2x = __ldg(vertices + 3 * id.z + 0);
        float v2y = __ldg(vertices + 3 * id.z + 1);
        float v2z = __ldg(vertices + 3 * id.z + 2);
        float v3x = __ldg(vertices + 3 * id.w + 0);
        float v3y = __ldg(vertices + 3 * id.w + 1);
        float v3z = __ldg(vertices + 3 * id.w + 2);

        {
            float bx = 0.25f * (v0x + v1x + v2x + v3x);
            float by = 0.25f * (v0y + v1y + v2y + v3y);
            float bz = 0.25f * (v0z + v1z + v2z + v3z);
            vdx = __ldg(camera + 0) - bx;
            vdy = __ldg(camera + 1) - by;
            vdz = __ldg(camera + 2) - bz;
            float vn = fmaxf(sqrtf(vdx * vdx + vdy * vdy + vdz * vdz), EPSF);
            vdx /= vn; vdy /= vn; vdz /= vn;
        }

        float a00 = 2.0f * (v1x - v0x) + 1e-6f;
        float a01 = 2.0f * (v1y - v0y);
        float a02 = 2.0f * (v1z - v0z);
        float a10 = 2.0f * (v2x - v0x);
        float a11 = 2.0f * (v2y - v0y) + 1e-6f;
        float a12 = 2.0f * (v2z - v0z);
        float a20 = 2.0f * (v3x - v0x);
        float a21 = 2.0f * (v3y - v0y);
        float a22 = 2.0f * (v3z - v0z) + 1e-6f;
        float r0 = (v1x * v1x - v0x * v0x) + (v1y * v1y - v0y * v0y) + (v1z * v1z - v0z * v0z);
        float r1 = (v2x * v2x - v0x * v0x) + (v2y * v2y - v0y * v0y) + (v2z * v2z - v0z * v0z);
        float r2 = (v3x * v3x - v0x * v0x) + (v3y * v3y - v0y * v0y) + (v3z * v3z - v0z * v0z);
        {
            float tmp;
            float m0 = fabsf(a00), m1a = fabsf(a10), m2a = fabsf(a20);
            if (m1a > m0 && m1a >= m2a) {
                tmp = a00; a00 = a10; a10 = tmp;
                tmp = a01; a01 = a11; a11 = tmp;
                tmp = a02; a02 = a12; a12 = tmp;
                tmp = r0;  r0  = r1;  r1  = tmp;
            } else if (m2a > m0) {
                tmp = a00; a00 = a20; a20 = tmp;
                tmp = a01; a01 = a21; a21 = tmp;
                tmp = a02; a02 = a22; a22 = tmp;
                tmp = r0;  r0  = r2;  r2  = tmp;
            }
            float f1 = a10 / a00, f2 = a20 / a00;
            a11 -= f1 * a01; a12 -= f1 * a02; r1 -= f1 * r0;
            a21 -= f2 * a01; a22 -= f2 * a02; r2 -= f2 * r0;
            if (fabsf(a21) > fabsf(a11)) {
                tmp = a11; a11 = a21; a21 = tmp;
                tmp = a12; a12 = a22; a22 = tmp;
                tmp = r1;  r1  = r2;  r2  = tmp;
            }
            float f3 = a21 / a11;
            a22 -= f3 * a12; r2 -= f3 * r1;
        }
        float ccz = r2 / a22;
        float ccy = (r1 - a12 * ccz) / a11;
        float ccx = (r0 - a01 * ccy - a02 * ccz) / a00;

        float radius = sqrtf((ccx - v0x) * (ccx - v0x) +
                             (ccy - v0y) * (ccy - v0y) +
                             (ccz - v0z) * (ccz - v0z));

        float ss  = __ldg(scalep);
        float nx  = (ccx - __ldg(centerp + 0)) / ss;
        float ny  = (ccy - __ldg(centerp + 1)) / ss;
        float nz  = (ccz - __ldg(centerp + 2)) / ss;
        float n   = fmaxf(sqrtf(nx * nx + ny * ny + nz * nz), EPSF);
        float cvx, cvy, cvz, fac;
        if (n <= 1.0f) {
            cvx = nx; cvy = ny; cvz = nz; fac = 1.0f;
        } else {
            float inv = 1.0f / n;
            float s2  = (2.0f - inv) * inv;
            cvx = nx * s2; cvy = ny * s2; cvz = nz * s2;
            fac = inv * inv;
        }
        float cr = radius / ss * fac * 0.5f;

        float hx = cvx * 0.25f + 0.5f;
        float hy = cvy * 0.25f + 0.5f;
        float hz = cvz * 0.25f + 0.5f;

        float* erow = senc + tid * ENC_PITCH;
#pragma unroll
        for (int l = 0; l < 10; ++l) {
            float resf = (float)(16 << l);
            float px = hx * resf, py = hy * resf, pz = hz * resf;
            float fx = floorf(px), fy = floorf(py), fz = floorf(pz);
            float wx = px - fx, wy = py - fy, wz = pz - fz;
            unsigned ux = (unsigned)(int)fx;
            unsigned uy = (unsigned)(int)fy;
            unsigned uz = (unsigned)(int)fz;
            unsigned ux1 = ux + 1u;
            unsigned hy0 = uy * 2654435761u, hy1 = (uy + 1u) * 2654435761u;
            unsigned hz0 = uz * 805459861u,  hz1 = (uz + 1u) * 805459861u;
            float wx0 = 1.0f - wx, wy0 = 1.0f - wy, wz0 = 1.0f - wz;
            const float4* tl = tables4 + ((size_t)l << 16);

            float4 c0 = __ldg(tl + ((ux  ^ hy0 ^ hz0) & 0xFFFFu));
            float4 c1 = __ldg(tl + ((ux  ^ hy0 ^ hz1) & 0xFFFFu));
            float4 c2 = __ldg(tl + ((ux  ^ hy1 ^ hz0) & 0xFFFFu));
            float4 c3 = __ldg(tl + ((ux  ^ hy1 ^ hz1) & 0xFFFFu));
            float4 c4 = __ldg(tl + ((ux1 ^ hy0 ^ hz0) & 0xFFFFu));
            float4 c5 = __ldg(tl + ((ux1 ^ hy0 ^ hz1) & 0xFFFFu));
            float4 c6 = __ldg(tl + ((ux1 ^ hy1 ^ hz0) & 0xFFFFu));
            float4 c7 = __ldg(tl + ((ux1 ^ hy1 ^ hz1) & 0xFFFFu));

            float w0 = wx0 * wy0 * wz0;
            float w1 = wx0 * wy0 * wz;
            float w2 = wx0 * wy  * wz0;
            float w3 = wx0 * wy  * wz;
            float w4 = wx  * wy0 * wz0;
            float w5 = wx  * wy0 * wz;
            float w6 = wx  * wy  * wz0;
            float w7 = wx  * wy  * wz;

            float ax = w0 * c0.x, ay = w0 * c0.y, az = w0 * c0.z, aw = w0 * c0.w;
            ax = fmaf(w1, c1.x, ax); ay = fmaf(w1, c1.y, ay); az = fmaf(w1, c1.z, az); aw = fmaf(w1, c1.w, aw);
            ax = fmaf(w2, c2.x, ax); ay = fmaf(w2, c2.y, ay); az = fmaf(w2, c2.z, az); aw = fmaf(w2, c2.w, aw);
            ax = fmaf(w3, c3.x, ax); ay = fmaf(w3, c3.y, ay); az = fmaf(w3, c3.z, az); aw = fmaf(w3, c3.w, aw);
            ax = fmaf(w4, c4.x, ax); ay = fmaf(w4, c4.y, ay); az = fmaf(w4, c4.z, az); aw = fmaf(w4, c4.w, aw);
            ax = fmaf(w5, c5.x, ax); ay = fmaf(w5, c5.y, ay); az = fmaf(w5, c5.z, az); aw = fmaf(w5, c5.w, aw);
            ax = fmaf(w6, c6.x, ax); ay = fmaf(w6, c6.y, ay); az = fmaf(w6, c6.z, az); aw = fmaf(w6, c6.w, aw);
            ax = fmaf(w7, c7.x, ax); ay = fmaf(w7, c7.y, ay); az = fmaf(w7, c7.z, az); aw = fmaf(w7, c7.w, aw);

            float denom = 8.0f * (float)l * cr;
            float sc = erff(rsqrtf(fmaxf(denom, EPSF)));
            erow[l]      = ax * sc;
            erow[10 + l] = ay * sc;
            erow[20 + l] = az * sc;
            erow[30 + l] = aw * sc;
        }
    }

    __syncwarp();   // rows [warp*32, warp*32+32) complete (warp-private tile)

    // ================= MLP phase (warp = 32 rows via 2 m-tiles) =================
#pragma unroll
    for (int mt = 0; mt < 2; ++mt) {
        const int rowbase = warp * 32 + mt * 16;
        const int ra = rowbase + g;        // local rows
        const int rb = ra + 8;

        // ---------------- layer 1: k=48 (padded), n=64, 96B rows ----------------
        float D1[8][4];
#pragma unroll
        for (int nt = 0; nt < 8; ++nt) { D1[nt][0] = 0; D1[nt][1] = 0; D1[nt][2] = 0; D1[nt][3] = 0; }

#pragma unroll
        for (int s = 0; s < 3; ++s) {
            int f0 = 16 * s + 2 * q;
            const float* ea = senc + ra * ENC_PITCH;
            const float* eb = senc + rb * ENC_PITCH;
            float va0 = (f0     < 40) ? ea[f0]     : 0.0f;
            float va1 = (f0 + 1 < 40) ? ea[f0 + 1] : 0.0f;
            float va8 = (f0 + 8 < 40) ? ea[f0 + 8] : 0.0f;
            float va9 = (f0 + 9 < 40) ? ea[f0 + 9] : 0.0f;
            float vb0 = (f0     < 40) ? eb[f0]     : 0.0f;
            float vb1 = (f0 + 1 < 40) ? eb[f0 + 1] : 0.0f;
            float vb8 = (f0 + 8 < 40) ? eb[f0 + 8] : 0.0f;
            float vb9 = (f0 + 9 < 40) ? eb[f0 + 9] : 0.0f;

            unsigned short h0, l0, h1, l1;
            uint32_t Ah[4], Al[4];
            splitbf(va0, h0, l0); splitbf(va1, h1, l1); Ah[0] = pk16(h0, h1); Al[0] = pk16(l0, l1);
            splitbf(vb0, h0, l0); splitbf(vb1, h1, l1); Ah[1] = pk16(h0, h1); Al[1] = pk16(l0, l1);
            splitbf(va8, h0, l0); splitbf(va9, h1, l1); Ah[2] = pk16(h0, h1); Al[2] = pk16(l0, l1);
            splitbf(vb8, h0, l0); splitbf(vb9, h1, l1); Ah[3] = pk16(h0, h1); Al[3] = pk16(l0, l1);

            int off0 = (((8 * s + q)     ^ g4) << 2);
            int off1 = (((8 * s + q + 4) ^ g4) << 2);
            const unsigned char* rbw = sm + OFF_W1H + g * 96;
#pragma unroll
            for (int nt = 0; nt < 8; ++nt) {
                uint32_t bh0 = *(const uint32_t*)(rbw + nt * 768 + off0);
                uint32_t bh1 = *(const uint32_t*)(rbw + nt * 768 + off1);
                uint32_t bl0 = *(const uint32_t*)(rbw + 6144 + nt * 768 + off0);
                uint32_t bl1 = *(const uint32_t*)(rbw + 6144 + nt * 768 + off1);
                mma_bf16(D1[nt], Ah[0], Ah[1], Ah[2], Ah[3], bh0, bh1);
                mma_bf16(D1[nt], Al[0], Al[1], Al[2], Al[3], bh0, bh1);
                mma_bf16(D1[nt], Ah[0], Ah[1], Ah[2], Ah[3], bl0, bl1);
            }
        }

        // ---------------- selu(D1+b1) -> A2 fragments ----------------
        uint32_t A2h[4][4], A2l[4][4];
#pragma unroll
        for (int s = 0; s < 4; ++s) {
            int c = 16 * s + 2 * q;
            float x00 = seluf(D1[2 * s][0]     + b1s[c]);
            float x01 = seluf(D1[2 * s][1]     + b1s[c + 1]);
            float x10 = seluf(D1[2 * s][2]     + b1s[c]);
            float x11 = seluf(D1[2 * s][3]     + b1s[c + 1]);
            float x20 = seluf(D1[2 * s + 1][0] + b1s[c + 8]);
            float x21 = seluf(D1[2 * s + 1][1] + b1s[c + 9]);
            float x30 = seluf(D1[2 * s + 1][2] + b1s[c + 8]);
            float x31 = seluf(D1[2 * s + 1][3] + b1s[c + 9]);
            unsigned short h0, l0, h1, l1;
            splitbf(x00, h0, l0); splitbf(x01, h1, l1); A2h[s][0] = pk16(h0, h1); A2l[s][0] = pk16(l0, l1);
            splitbf(x10, h0, l0); splitbf(x11, h1, l1); A2h[s][1] = pk16(h0, h1); A2l[s][1] = pk16(l0, l1);
            splitbf(x20, h0, l0); splitbf(x21, h1, l1); A2h[s][2] = pk16(h0, h1); A2l[s][2] = pk16(l0, l1);
            splitbf(x30, h0, l0); splitbf(x31, h1, l1); A2h[s][3] = pk16(h0, h1); A2l[s][3] = pk16(l0, l1);
        }

        // ---------------- layer 2: k=64, n=64 ----------------
        float D2[8][4];
#pragma unroll
        for (int nt = 0; nt < 8; ++nt) { D2[nt][0] = 0; D2[nt][1] = 0; D2[nt][2] = 0; D2[nt][3] = 0; }
#pragma unroll
        for (int s = 0; s < 4; ++s) {
            int off0 = (((8 * s + q)     << 2) ^ gx);
            int off1 = (((8 * s + q + 4) << 2) ^ gx);
            const unsigned char* rbw = sm + OFF_W2H + g * 128;
#pragma unroll
            for (int nt = 0; nt < 8; ++nt) {
                uint32_t bh0 = *(const uint32_t*)(rbw + nt * 1024 + off0);
                uint32_t bh1 = *(const uint32_t*)(rbw + nt * 1024 + off1);
                uint32_t bl0 = *(const uint32_t*)(rbw + 8192 + nt * 1024 + off0);
                uint32_t bl1 = *(const uint32_t*)(rbw + 8192 + nt * 1024 + off1);
                mma_bf16(D2[nt], A2h[s][0], A2h[s][1], A2h[s][2], A2h[s][3], bh0, bh1);
                mma_bf16(D2[nt], A2l[s][0], A2l[s][1], A2l[s][2], A2l[s][3], bh0, bh1);
                mma_bf16(D2[nt], A2h[s][0], A2h[s][1], A2h[s][2], A2h[s][3], bl0, bl1);
            }
        }

        // ---------------- selu(D2+b2) -> A3 fragments ----------------
        uint32_t A3h[4][4], A3l[4][4];
#pragma unroll
        for (int s = 0; s < 4; ++s) {
            int c = 16 * s + 2 * q;
            float x00 = seluf(D2[2 * s][0]     + b2s[c]);
            float x01 = seluf(D2[2 * s][1]     + b2s[c + 1]);
            float x10 = seluf(D2[2 * s][2]     + b2s[c]);
            float x11 = seluf(D2[2 * s][3]     + b2s[c + 1]);
            float x20 = seluf(D2[2 * s + 1][0] + b2s[c + 8]);
            float x21 = seluf(D2[2 * s + 1][1] + b2s[c + 9]);
            float x30 = seluf(D2[2 * s + 1][2] + b2s[c + 8]);
            float x31 = seluf(D2[2 * s + 1][3] + b2s[c + 9]);
            unsigned short h0, l0, h1, l1;
            splitbf(x00, h0, l0); splitbf(x01, h1, l1); A3h[s][0] = pk16(h0, h1); A3l[s][0] = pk16(l0, l1);
            splitbf(x10, h0, l0); splitbf(x11, h1, l1); A3h[s][1] = pk16(h0, h1); A3l[s][1] = pk16(l0, l1);
            splitbf(x20, h0, l0); splitbf(x21, h1, l1); A3h[s][2] = pk16(h0, h1); A3l[s][2] = pk16(l0, l1);
            splitbf(x30, h0, l0); splitbf(x31, h1, l1); A3h[s][3] = pk16(h0, h1); A3l[s][3] = pk16(l0, l1);
        }

        // ---------------- layer 3: k=64, n=16 ----------------
        float D3[2][4];
        D3[0][0] = D3[0][1] = D3[0][2] = D3[0][3] = 0;
        D3[1][0] = D3[1][1] = D3[1][2] = D3[1][3] = 0;
#pragma unroll
        for (int s = 0; s < 4; ++s) {
            int off0 = (((8 * s + q)     << 2) ^ gx);
            int off1 = (((8 * s + q + 4) << 2) ^ gx);
            const unsigned char* rbw = sm + OFF_W3H + g * 128;
#pragma unroll
            for (int nt = 0; nt < 2; ++nt) {
                uint32_t bh0 = *(const uint32_t*)(rbw + nt * 1024 + off0);
                uint32_t bh1 = *(const uint32_t*)(rbw + nt * 1024 + off1);
                uint32_t bl0 = *(const uint32_t*)(rbw + 2048 + nt * 1024 + off0);
                uint32_t bl1 = *(const uint32_t*)(rbw + 2048 + nt * 1024 + off1);
                mma_bf16(D3[nt], A3h[s][0], A3h[s][1], A3h[s][2], A3h[s][3], bh0, bh1);
                mma_bf16(D3[nt], A3l[s][0], A3l[s][1], A3l[s][2], A3l[s][3], bh0, bh1);
                mma_bf16(D3[nt], A3h[s][0], A3h[s][1], A3h[s][2], A3h[s][3], bl0, bl1);
            }
        }

        // ---- store D3 + b3 into enc rows (cols 0..15; rows already consumed) ----
        __syncwarp();
        {
            int c0 = 2 * q;
            float* oa = senc + ra * ENC_PITCH;
            float* ob = senc + rb * ENC_PITCH;
            oa[c0]     = D3[0][0] + b3s[c0];
            oa[c0 + 1] = D3[0][1] + b3s[c0 + 1];
            oa[c0 + 8] = D3[1][0] + b3s[c0 + 8];
            oa[c0 + 9] = D3[1][1] + b3s[c0 + 9];
            ob[c0]     = D3[0][2] + b3s[c0];
            ob[c0 + 1] = D3[0][3] + b3s[c0 + 1];
            ob[c0 + 8] = D3[1][2] + b3s[c0 + 8];
            ob[c0 + 9] = D3[1][3] + b3s[c0 + 9];
        }
    }

    __syncwarp();

    // ================= lighting epilogue (thread = own tet/row) =================
    {
        int t = t0 + tid;
        float o[16];
#pragma unroll
        for (int j = 0; j < 16; ++j) o[j] = senc[tid * ENC_PITCH + j];

        float out0 = softplusf(o[0]);
        float out1 = softplusf(o[1]);
        float out2 = softplusf(o[2]);
#pragma unroll
        for (int k = 0; k < 2; ++k) {
            const int b = 4 + 6 * k;
            float lc0 = softplusf(o[b + 0] - 3.0f);
            float lc1 = softplusf(o[b + 1] - 3.0f);
            float lc2 = softplusf(o[b + 2] - 3.0f);
            float e = o[b + 3] - 1.0f;
            e = fminf(fmaxf(e, -30.0f), 15.0f);
            float rough = 4.0f * fminf(expf(e), 100.0f);
            float rd0 = o[b + 4] + (k ? 3.14159265358979323846f : 0.0f);
            float rd1 = o[b + 5];
            float s0, c0, s1, c1;
            sincosf(rd0, &s0, &c0);
            sincosf(rd1, &s1, &c1);
            float rx = c0 * s1, ry = s0 * s1, rz = c1;
            float sim = rx * vdx + ry * vdy + rz * vdz;
            float spec = (sim > 0.0f) ? powf(fmaxf(sim, EPSF), rough) : 0.0f;
            out0 = fmaf(lc0, spec, out0);
            out1 = fmaf(lc1, spec, out1);
            out2 = fmaf(lc2, spec, out2);
        }
        if (t < T) {
            outp[3 * t + 0] = out0;
            outp[3 * t + 1] = out1;
            outp[3 * t + 2] = out2;
        }
    }
}

extern "C" void kernel_launch(void* const* d_in, const int* in_sizes, int n_in,
                              void* d_out, int out_size)
{
    const float*  vertices = (const float*)d_in[0];
    const int4*   indices  = (const int4*)d_in[1];
    const float*  camera   = (const float*)d_in[2];
    const float4* tables   = (const float4*)d_in[3];
    const float*  W1 = (const float*)d_in[4];
    const float*  B1 = (const float*)d_in[5];
    const float*  W2 = (const float*)d_in[6];
    const float*  B2 = (const float*)d_in[7];
    const float*  W3 = (const float*)d_in[8];
    const float*  B3 = (const float*)d_in[9];
    const float*  center = (const float*)d_in[10];
    const float*  scale  = (const float*)d_in[11];

    int T = in_sizes[1] / 4;
    int grid = (T + NTH - 1) / NTH;

    static bool attr_set = false;
    if (!attr_set) {
        cudaFuncSetAttribute(fused_kernel,
                             cudaFuncAttributeMaxDynamicSharedMemorySize, SMEM_SZ);
        attr_set = true;
    }

    fused_kernel<<<grid, NTH, SMEM_SZ>>>(vertices, indices, camera, tables,
                                         W1, B1, W2, B2, W3, B3,
                                         center, scale, (float*)d_out, T);
}

// round 15
// speedup vs baseline: 1.4470x; 1.4470x over previous
#include <cuda_runtime.h>
#include <cuda_bf16.h>
#include <math.h>
#include <cstdint>

#define NTH 320

static __device__ __forceinline__ float seluf(float x) {
    const float lam    = 1.0507009873554805f;
    const float lamalp = 1.7580993408473766f;
    float e = __expf(x) - 1.0f;
    return x > 0.0f ? lam * x : lamalp * e;
}
static __device__ __forceinline__ float softplusf(float x) {
    return fmaxf(x, 0.0f) + log1pf(expf(-fabsf(x)));
}

static __device__ __forceinline__ void splitbf(float v, unsigned short& h, unsigned short& l) {
    __nv_bfloat16 hb = __float2bfloat16(v);
    float r = v - __bfloat162float(hb);
    __nv_bfloat16 lb = __float2bfloat16(r);
    h = __bfloat16_as_ushort(hb);
    l = __bfloat16_as_ushort(lb);
}
static __device__ __forceinline__ uint32_t pk16(unsigned short a, unsigned short b) {
    return (uint32_t)a | ((uint32_t)b << 16);
}

static __device__ __forceinline__ void mma_bf16(float d[4],
    uint32_t a0, uint32_t a1, uint32_t a2, uint32_t a3, uint32_t b0, uint32_t b1)
{
    asm volatile(
        "mma.sync.aligned.m16n8k16.row.col.f32.bf16.bf16.f32 "
        "{%0,%1,%2,%3}, {%4,%5,%6,%7}, {%8,%9}, {%0,%1,%2,%3};\n"
        : "+f"(d[0]), "+f"(d[1]), "+f"(d[2]), "+f"(d[3])
        : "r"(a0), "r"(a1), "r"(a2), "r"(a3), "r"(b0), "r"(b1));
}

// SMEM layout (bytes) — identical weight layout to R13 (proven)
#define OFF_W1H 0
#define OFF_W1L 8192
#define OFF_W2H 16384
#define OFF_W2L 24576
#define OFF_W3H 32768
#define OFF_W3L 34816
#define OFF_B1  36864
#define OFF_B2  37120
#define OFF_B3  37376
#define OFF_ENC 37440                  // 320 rows x 41 floats = 52,480 B
#define SMEM_SZ 89920

#define ENC_PITCH 41

__global__ void __launch_bounds__(NTH, 2)
fused_kernel(
    const float*  __restrict__ vertices,
    const int4*   __restrict__ indices,
    const float*  __restrict__ camera,
    const float4* __restrict__ tables4,
    const float*  __restrict__ W1, const float* __restrict__ B1,
    const float*  __restrict__ W2, const float* __restrict__ B2,
    const float*  __restrict__ W3, const float* __restrict__ B3,
    const float*  __restrict__ centerp,
    const float*  __restrict__ scalep,
    float*        __restrict__ outp,
    int T)
{
    extern __shared__ __align__(16) unsigned char sm[];
    const int tid  = threadIdx.x;
    const int lane = tid & 31;
    const int warp = tid >> 5;
    const int g    = lane >> 2;
    const int q    = lane & 3;
    const int gx   = g << 4;

    // ---- zero W1 region (covers k padding 40..47) ----
    for (int i = tid; i < 16384 / 4; i += NTH) ((uint32_t*)sm)[i] = 0;
    __syncthreads();

    // ---- stage weights: pairs of k per u32 word, XOR-swizzled 128B rows ----
    for (int p = tid; p < 20 * 64; p += NTH) {           // W1
        int j = p & 63, i0 = (p >> 6) << 1;
        unsigned short h0, l0, h1, l1;
        splitbf(W1[i0 * 64 + j],      h0, l0);
        splitbf(W1[i0 * 64 + 64 + j], h1, l1);
        int w = i0 >> 1;
        int byte = j * 128 + (((w << 2) ^ ((j & 7) << 4)));
        *(uint32_t*)(sm + OFF_W1H + byte) = pk16(h0, h1);
        *(uint32_t*)(sm + OFF_W1L + byte) = pk16(l0, l1);
    }
    for (int p = tid; p < 32 * 64; p += NTH) {           // W2
        int j = p & 63, i0 = (p >> 6) << 1;
        unsigned short h0, l0, h1, l1;
        splitbf(W2[i0 * 64 + j],      h0, l0);
        splitbf(W2[i0 * 64 + 64 + j], h1, l1);
        int w = i0 >> 1;
        int byte = j * 128 + (((w << 2) ^ ((j & 7) << 4)));
        *(uint32_t*)(sm + OFF_W2H + byte) = pk16(h0, h1);
        *(uint32_t*)(sm + OFF_W2L + byte) = pk16(l0, l1);
    }
    for (int p = tid; p < 32 * 16; p += NTH) {           // W3
        int j = p & 15, i0 = (p >> 4) << 1;
        unsigned short h0, l0, h1, l1;
        splitbf(W3[i0 * 16 + j],      h0, l0);
        splitbf(W3[i0 * 16 + 16 + j], h1, l1);
        int w = i0 >> 1;
        int byte = j * 128 + (((w << 2) ^ ((j & 7) << 4)));
        *(uint32_t*)(sm + OFF_W3H + byte) = pk16(h0, h1);
        *(uint32_t*)(sm + OFF_W3L + byte) = pk16(l0, l1);
    }
    if (tid < 64) {
        ((float*)(sm + OFF_B1))[tid] = B1[tid];
        ((float*)(sm + OFF_B2))[tid] = B2[tid];
    }
    if (tid < 16) ((float*)(sm + OFF_B3))[tid] = B3[tid];
    __syncthreads();

    const float* b1s = (const float*)(sm + OFF_B1);
    const float* b2s = (const float*)(sm + OFF_B2);
    const float* b3s = (const float*)(sm + OFF_B3);
    float* senc = (float*)(sm + OFF_ENC);

    const int t0 = blockIdx.x * NTH;
    const float EPSF = 1.1920928955078125e-07f;

    // ================= enc phase (thread = tet t0+tid, row tid) =================
    float vdx, vdy, vdz;
    {
        int t = t0 + tid;
        int tc = (t < T) ? t : (T - 1);

        int4 id = indices[tc];
        float v0x = __ldg(vertices + 3 * id.x + 0);
        float v0y = __ldg(vertices + 3 * id.x + 1);
        float v0z = __ldg(vertices + 3 * id.x + 2);
        float v1x = __ldg(vertices + 3 * id.y + 0);
        float v1y = __ldg(vertices + 3 * id.y + 1);
        float v1z = __ldg(vertices + 3 * id.y + 2);
        float v2x = __ldg(vertices + 3 * id.z + 0);
        float v2y = __ldg(vertices + 3 * id.z + 1);
        float v2z = __ldg(vertices + 3 * id.z + 2);
        float v3x = __ldg(vertices + 3 * id.w + 0);
        float v3y = __ldg(vertices + 3 * id.w + 1);
        float v3z = __ldg(vertices + 3 * id.w + 2);

        {
            float bx = 0.25f * (v0x + v1x + v2x + v3x);
            float by = 0.25f * (v0y + v1y + v2y + v3y);
            float bz = 0.25f * (v0z + v1z + v2z + v3z);
            vdx = __ldg(camera + 0) - bx;
            vdy = __ldg(camera + 1) - by;
            vdz = __ldg(camera + 2) - bz;
            float vn = fmaxf(sqrtf(vdx * vdx + vdy * vdy + vdz * vdz), EPSF);
            vdx /= vn; vdy /= vn; vdz /= vn;
        }

        float a00 = 2.0f * (v1x - v0x) + 1e-6f;
        float a01 = 2.0f * (v1y - v0y);
        float a02 = 2.0f * (v1z - v0z);
        float a10 = 2.0f * (v2x - v0x);
        float a11 = 2.0f * (v2y - v0y) + 1e-6f;
        float a12 = 2.0f * (v2z - v0z);
        float a20 = 2.0f * (v3x - v0x);
        float a21 = 2.0f * (v3y - v0y);
        float a22 = 2.0f * (v3z - v0z) + 1e-6f;
        float r0 = (v1x * v1x - v0x * v0x) + (v1y * v1y - v0y * v0y) + (v1z * v1z - v0z * v0z);
        float r1 = (v2x * v2x - v0x * v0x) + (v2y * v2y - v0y * v0y) + (v2z * v2z - v0z * v0z);
        float r2 = (v3x * v3x - v0x * v0x) + (v3y * v3y - v0y * v0y) + (v3z * v3z - v0z * v0z);
        {
            float tmp;
            float m0 = fabsf(a00), m1a = fabsf(a10), m2a = fabsf(a20);
            if (m1a > m0 && m1a >= m2a) {
                tmp = a00; a00 = a10; a10 = tmp;
                tmp = a01; a01 = a11; a11 = tmp;
                tmp = a02; a02 = a12; a12 = tmp;
                tmp = r0;  r0  = r1;  r1  = tmp;
            } else if (m2a > m0) {
                tmp = a00; a00 = a20; a20 = tmp;
                tmp = a01; a01 = a21; a21 = tmp;
                tmp = a02; a02 = a22; a22 = tmp;
                tmp = r0;  r0  = r2;  r2  = tmp;
            }
            float f1 = a10 / a00, f2 = a20 / a00;
            a11 -= f1 * a01; a12 -= f1 * a02; r1 -= f1 * r0;
            a21 -= f2 * a01; a22 -= f2 * a02; r2 -= f2 * r0;
            if (fabsf(a21) > fabsf(a11)) {
                tmp = a11; a11 = a21; a21 = tmp;
                tmp = a12; a12 = a22; a22 = tmp;
                tmp = r1;  r1  = r2;  r2  = tmp;
            }
            float f3 = a21 / a11;
            a22 -= f3 * a12; r2 -= f3 * r1;
        }
        float ccz = r2 / a22;
        float ccy = (r1 - a12 * ccz) / a11;
        float ccx = (r0 - a01 * ccy - a02 * ccz) / a00;

        float radius = sqrtf((ccx - v0x) * (ccx - v0x) +
                             (ccy - v0y) * (ccy - v0y) +
                             (ccz - v0z) * (ccz - v0z));

        float ss  = __ldg(scalep);
        float nx  = (ccx - __ldg(centerp + 0)) / ss;
        float ny  = (ccy - __ldg(centerp + 1)) / ss;
        float nz  = (ccz - __ldg(centerp + 2)) / ss;
        float n   = fmaxf(sqrtf(nx * nx + ny * ny + nz * nz), EPSF);
        float cvx, cvy, cvz, fac;
        if (n <= 1.0f) {
            cvx = nx; cvy = ny; cvz = nz; fac = 1.0f;
        } else {
            float inv = 1.0f / n;
            float s2  = (2.0f - inv) * inv;
            cvx = nx * s2; cvy = ny * s2; cvz = nz * s2;
            fac = inv * inv;
        }
        float cr = radius / ss * fac * 0.5f;

        float hx = cvx * 0.25f + 0.5f;
        float hy = cvy * 0.25f + 0.5f;
        float hz = cvz * 0.25f + 0.5f;

        float* erow = senc + tid * ENC_PITCH;
#pragma unroll
        for (int l = 0; l < 10; ++l) {
            float resf = (float)(16 << l);
            float px = hx * resf, py = hy * resf, pz = hz * resf;
            float fx = floorf(px), fy = floorf(py), fz = floorf(pz);
            float wx = px - fx, wy = py - fy, wz = pz - fz;
            unsigned ux = (unsigned)(int)fx;
            unsigned uy = (unsigned)(int)fy;
            unsigned uz = (unsigned)(int)fz;
            unsigned ux1 = ux + 1u;
            unsigned hy0 = uy * 2654435761u, hy1 = (uy + 1u) * 2654435761u;
            unsigned hz0 = uz * 805459861u,  hz1 = (uz + 1u) * 805459861u;
            float wx0 = 1.0f - wx, wy0 = 1.0f - wy, wz0 = 1.0f - wz;
            const float4* tl = tables4 + ((size_t)l << 16);

            float4 c0 = __ldg(tl + ((ux  ^ hy0 ^ hz0) & 0xFFFFu));
            float4 c1 = __ldg(tl + ((ux  ^ hy0 ^ hz1) & 0xFFFFu));
            float4 c2 = __ldg(tl + ((ux  ^ hy1 ^ hz0) & 0xFFFFu));
            float4 c3 = __ldg(tl + ((ux  ^ hy1 ^ hz1) & 0xFFFFu));
            float4 c4 = __ldg(tl + ((ux1 ^ hy0 ^ hz0) & 0xFFFFu));
            float4 c5 = __ldg(tl + ((ux1 ^ hy0 ^ hz1) & 0xFFFFu));
            float4 c6 = __ldg(tl + ((ux1 ^ hy1 ^ hz0) & 0xFFFFu));
            float4 c7 = __ldg(tl + ((ux1 ^ hy1 ^ hz1) & 0xFFFFu));

            float w0 = wx0 * wy0 * wz0;
            float w1 = wx0 * wy0 * wz;
            float w2 = wx0 * wy  * wz0;
            float w3 = wx0 * wy  * wz;
            float w4 = wx  * wy0 * wz0;
            float w5 = wx  * wy0 * wz;
            float w6 = wx  * wy  * wz0;
            float w7 = wx  * wy  * wz;

            float ax = w0 * c0.x, ay = w0 * c0.y, az = w0 * c0.z, aw = w0 * c0.w;
            ax = fmaf(w1, c1.x, ax); ay = fmaf(w1, c1.y, ay); az = fmaf(w1, c1.z, az); aw = fmaf(w1, c1.w, aw);
            ax = fmaf(w2, c2.x, ax); ay = fmaf(w2, c2.y, ay); az = fmaf(w2, c2.z, az); aw = fmaf(w2, c2.w, aw);
            ax = fmaf(w3, c3.x, ax); ay = fmaf(w3, c3.y, ay); az = fmaf(w3, c3.z, az); aw = fmaf(w3, c3.w, aw);
            ax = fmaf(w4, c4.x, ax); ay = fmaf(w4, c4.y, ay); az = fmaf(w4, c4.z, az); aw = fmaf(w4, c4.w, aw);
            ax = fmaf(w5, c5.x, ax); ay = fmaf(w5, c5.y, ay); az = fmaf(w5, c5.z, az); aw = fmaf(w5, c5.w, aw);
            ax = fmaf(w6, c6.x, ax); ay = fmaf(w6, c6.y, ay); az = fmaf(w6, c6.z, az); aw = fmaf(w6, c6.w, aw);
            ax = fmaf(w7, c7.x, ax); ay = fmaf(w7, c7.y, ay); az = fmaf(w7, c7.z, az); aw = fmaf(w7, c7.w, aw);

            float denom = 8.0f * (float)l * cr;
            float sc = erff(rsqrtf(fmaxf(denom, EPSF)));
            erow[l]      = ax * sc;
            erow[10 + l] = ay * sc;
            erow[20 + l] = az * sc;
            erow[30 + l] = aw * sc;
        }
    }

    __syncwarp();   // rows [warp*32, warp*32+32) complete (warp-private tile)

    // ================= MLP phase (warp = 32 rows via 2 m-tiles) =================
#pragma unroll
    for (int mt = 0; mt < 2; ++mt) {
        const int rowbase = warp * 32 + mt * 16;
        const int ra = rowbase + g;        // local rows
        const int rb = ra + 8;

        // ---------------- layer 1: k=48 (padded), n=64 ----------------
        float D1[8][4];
#pragma unroll
        for (int nt = 0; nt < 8; ++nt) { D1[nt][0] = 0; D1[nt][1] = 0; D1[nt][2] = 0; D1[nt][3] = 0; }

#pragma unroll
        for (int s = 0; s < 3; ++s) {
            int f0 = 16 * s + 2 * q;
            const float* ea = senc + ra * ENC_PITCH;
            const float* eb = senc + rb * ENC_PITCH;
            float va0 = (f0     < 40) ? ea[f0]     : 0.0f;
            float va1 = (f0 + 1 < 40) ? ea[f0 + 1] : 0.0f;
            float va8 = (f0 + 8 < 40) ? ea[f0 + 8] : 0.0f;
            float va9 = (f0 + 9 < 40) ? ea[f0 + 9] : 0.0f;
            float vb0 = (f0     < 40) ? eb[f0]     : 0.0f;
            float vb1 = (f0 + 1 < 40) ? eb[f0 + 1] : 0.0f;
            float vb8 = (f0 + 8 < 40) ? eb[f0 + 8] : 0.0f;
            float vb9 = (f0 + 9 < 40) ? eb[f0 + 9] : 0.0f;

            unsigned short h0, l0, h1, l1;
            uint32_t Ah[4], Al[4];
            splitbf(va0, h0, l0); splitbf(va1, h1, l1); Ah[0] = pk16(h0, h1); Al[0] = pk16(l0, l1);
            splitbf(vb0, h0, l0); splitbf(vb1, h1, l1); Ah[1] = pk16(h0, h1); Al[1] = pk16(l0, l1);
            splitbf(va8, h0, l0); splitbf(va9, h1, l1); Ah[2] = pk16(h0, h1); Al[2] = pk16(l0, l1);
            splitbf(vb8, h0, l0); splitbf(vb9, h1, l1); Ah[3] = pk16(h0, h1); Al[3] = pk16(l0, l1);

            int off0 = (((8 * s + q)     << 2) ^ gx);
            int off1 = (((8 * s + q + 4) << 2) ^ gx);
            const unsigned char* rbw = sm + OFF_W1H + g * 128;
#pragma unroll
            for (int nt = 0; nt < 8; ++nt) {
                uint32_t bh0 = *(const uint32_t*)(rbw + nt * 1024 + off0);
                uint32_t bh1 = *(const uint32_t*)(rbw + nt * 1024 + off1);
                uint32_t bl0 = *(const uint32_t*)(rbw + 8192 + nt * 1024 + off0);
                uint32_t bl1 = *(const uint32_t*)(rbw + 8192 + nt * 1024 + off1);
                mma_bf16(D1[nt], Ah[0], Ah[1], Ah[2], Ah[3], bh0, bh1);
                mma_bf16(D1[nt], Al[0], Al[1], Al[2], Al[3], bh0, bh1);
                mma_bf16(D1[nt], Ah[0], Ah[1], Ah[2], Ah[3], bl0, bl1);
            }
        }

        // ---------------- selu(D1+b1) -> A2 fragments ----------------
        uint32_t A2h[4][4], A2l[4][4];
#pragma unroll
        for (int s = 0; s < 4; ++s) {
            int c = 16 * s + 2 * q;
            float x00 = seluf(D1[2 * s][0]     + b1s[c]);
            float x01 = seluf(D1[2 * s][1]     + b1s[c + 1]);
            float x10 = seluf(D1[2 * s][2]     + b1s[c]);
            float x11 = seluf(D1[2 * s][3]     + b1s[c + 1]);
            float x20 = seluf(D1[2 * s + 1][0] + b1s[c + 8]);
            float x21 = seluf(D1[2 * s + 1][1] + b1s[c + 9]);
            float x30 = seluf(D1[2 * s + 1][2] + b1s[c + 8]);
            float x31 = seluf(D1[2 * s + 1][3] + b1s[c + 9]);
            unsigned short h0, l0, h1, l1;
            splitbf(x00, h0, l0); splitbf(x01, h1, l1); A2h[s][0] = pk16(h0, h1); A2l[s][0] = pk16(l0, l1);
            splitbf(x10, h0, l0); splitbf(x11, h1, l1); A2h[s][1] = pk16(h0, h1); A2l[s][1] = pk16(l0, l1);
            splitbf(x20, h0, l0); splitbf(x21, h1, l1); A2h[s][2] = pk16(h0, h1); A2l[s][2] = pk16(l0, l1);
            splitbf(x30, h0, l0); splitbf(x31, h1, l1); A2h[s][3] = pk16(h0, h1); A2l[s][3] = pk16(l0, l1);
        }

        // ---------------- layer 2: k=64, n=64 ----------------
        float D2[8][4];
#pragma unroll
        for (int nt = 0; nt < 8; ++nt) { D2[nt][0] = 0; D2[nt][1] = 0; D2[nt][2] = 0; D2[nt][3] = 0; }
#pragma unroll
        for (int s = 0; s < 4; ++s) {
            int off0 = (((8 * s + q)     << 2) ^ gx);
            int off1 = (((8 * s + q + 4) << 2) ^ gx);
            const unsigned char* rbw = sm + OFF_W2H + g * 128;
#pragma unroll
            for (int nt = 0; nt < 8; ++nt) {
                uint32_t bh0 = *(const uint32_t*)(rbw + nt * 1024 + off0);
                uint32_t bh1 = *(const uint32_t*)(rbw + nt * 1024 + off1);
                uint32_t bl0 = *(const uint32_t*)(rbw + 8192 + nt * 1024 + off0);
                uint32_t bl1 = *(const uint32_t*)(rbw + 8192 + nt * 1024 + off1);
                mma_bf16(D2[nt], A2h[s][0], A2h[s][1], A2h[s][2], A2h[s][3], bh0, bh1);
                mma_bf16(D2[nt], A2l[s][0], A2l[s][1], A2l[s][2], A2l[s][3], bh0, bh1);
                mma_bf16(D2[nt], A2h[s][0], A2h[s][1], A2h[s][2], A2h[s][3], bl0, bl1);
            }
        }

        // ---------------- selu(D2+b2) -> A3 fragments ----------------
        uint32_t A3h[4][4], A3l[4][4];
#pragma unroll
        for (int s = 0; s < 4; ++s) {
            int c = 16 * s + 2 * q;
            float x00 = seluf(D2[2 * s][0]     + b2s[c]);
            float x01 = seluf(D2[2 * s][1]     + b2s[c + 1]);
            float x10 = seluf(D2[2 * s][2]     + b2s[c]);
            float x11 = seluf(D2[2 * s][3]     + b2s[c + 1]);
            float x20 = seluf(D2[2 * s + 1][0] + b2s[c + 8]);
            float x21 = seluf(D2[2 * s + 1][1] + b2s[c + 9]);
            float x30 = seluf(D2[2 * s + 1][2] + b2s[c + 8]);
            float x31 = seluf(D2[2 * s + 1][3] + b2s[c + 9]);
            unsigned short h0, l0, h1, l1;
            splitbf(x00, h0, l0); splitbf(x01, h1, l1); A3h[s][0] = pk16(h0, h1); A3l[s][0] = pk16(l0, l1);
            splitbf(x10, h0, l0); splitbf(x11, h1, l1); A3h[s][1] = pk16(h0, h1); A3l[s][1] = pk16(l0, l1);
            splitbf(x20, h0, l0); splitbf(x21, h1, l1); A3h[s][2] = pk16(h0, h1); A3l[s][2] = pk16(l0, l1);
            splitbf(x30, h0, l0); splitbf(x31, h1, l1); A3h[s][3] = pk16(h0, h1); A3l[s][3] = pk16(l0, l1);
        }

        // ---------------- layer 3: k=64, n=16 ----------------
        float D3[2][4];
        D3[0][0] = D3[0][1] = D3[0][2] = D3[0][3] = 0;
        D3[1][0] = D3[1][1] = D3[1][2] = D3[1][3] = 0;
#pragma unroll
        for (int s = 0; s < 4; ++s) {
            int off0 = (((8 * s + q)     << 2) ^ gx);
            int off1 = (((8 * s + q + 4) << 2) ^ gx);
            const unsigned char* rbw = sm + OFF_W3H + g * 128;
#pragma unroll
            for (int nt = 0; nt < 2; ++nt) {
                uint32_t bh0 = *(const uint32_t*)(rbw + nt * 1024 + off0);
                uint32_t bh1 = *(const uint32_t*)(rbw + nt * 1024 + off1);
                uint32_t bl0 = *(const uint32_t*)(rbw + 2048 + nt * 1024 + off0);
                uint32_t bl1 = *(const uint32_t*)(rbw + 2048 + nt * 1024 + off1);
                mma_bf16(D3[nt], A3h[s][0], A3h[s][1], A3h[s][2], A3h[s][3], bh0, bh1);
                mma_bf16(D3[nt], A3l[s][0], A3l[s][1], A3l[s][2], A3l[s][3], bh0, bh1);
                mma_bf16(D3[nt], A3h[s][0], A3h[s][1], A3h[s][2], A3h[s][3], bl0, bl1);
            }
        }

        // ---- store D3 + b3 into enc rows (cols 0..15; rows already consumed) ----
        __syncwarp();
        {
            int c0 = 2 * q;
            float* oa = senc + ra * ENC_PITCH;
            float* ob = senc + rb * ENC_PITCH;
            oa[c0]     = D3[0][0] + b3s[c0];
            oa[c0 + 1] = D3[0][1] + b3s[c0 + 1];
            oa[c0 + 8] = D3[1][0] + b3s[c0 + 8];
            oa[c0 + 9] = D3[1][1] + b3s[c0 + 9];
            ob[c0]     = D3[0][2] + b3s[c0];
            ob[c0 + 1] = D3[0][3] + b3s[c0 + 1];
            ob[c0 + 8] = D3[1][2] + b3s[c0 + 8];
            ob[c0 + 9] = D3[1][3] + b3s[c0 + 9];
        }
    }

    __syncwarp();

    // ================= lighting epilogue (thread = own tet/row) =================
    {
        int t = t0 + tid;
        float o[16];
#pragma unroll
        for (int j = 0; j < 16; ++j) o[j] = senc[tid * ENC_PITCH + j];

        float out0 = softplusf(o[0]);
        float out1 = softplusf(o[1]);
        float out2 = softplusf(o[2]);
#pragma unroll
        for (int k = 0; k < 2; ++k) {
            const int b = 4 + 6 * k;
            float lc0 = softplusf(o[b + 0] - 3.0f);
            float lc1 = softplusf(o[b + 1] - 3.0f);
            float lc2 = softplusf(o[b + 2] - 3.0f);
            float e = o[b + 3] - 1.0f;
            e = fminf(fmaxf(e, -30.0f), 15.0f);
            float rough = 4.0f * fminf(__expf(e), 100.0f);
            float rd0 = o[b + 4] + (k ? 3.14159265358979323846f : 0.0f);
            float rd1 = o[b + 5];
            float s0, c0, s1, c1;
            __sincosf(rd0, &s0, &c0);
            __sincosf(rd1, &s1, &c1);
            float rx = c0 * s1, ry = s0 * s1, rz = c1;
            float sim = rx * vdx + ry * vdy + rz * vdz;
            float spec = (sim > 0.0f) ? __powf(fmaxf(sim, EPSF), rough) : 0.0f;
            out0 = fmaf(lc0, spec, out0);
            out1 = fmaf(lc1, spec, out1);
            out2 = fmaf(lc2, spec, out2);
        }
        if (t < T) {
            outp[3 * t + 0] = out0;
            outp[3 * t + 1] = out1;
            outp[3 * t + 2] = out2;
        }
    }
}

extern "C" void kernel_launch(void* const* d_in, const int* in_sizes, int n_in,
                              void* d_out, int out_size)
{
    const float*  vertices = (const float*)d_in[0];
    const int4*   indices  = (const int4*)d_in[1];
    const float*  camera   = (const float*)d_in[2];
    const float4* tables   = (const float4*)d_in[3];
    const float*  W1 = (const float*)d_in[4];
    const float*  B1 = (const float*)d_in[5];
    const float*  W2 = (const float*)d_in[6];
    const float*  B2 = (const float*)d_in[7];
    const float*  W3 = (const float*)d_in[8];
    const float*  B3 = (const float*)d_in[9];
    const float*  center = (const float*)d_in[10];
    const float*  scale  = (const float*)d_in[11];

    int T = in_sizes[1] / 4;
    int grid = (T + NTH - 1) / NTH;

    static bool attr_set = false;
    if (!attr_set) {
        cudaFuncSetAttribute(fused_kernel,
                             cudaFuncAttributeMaxDynamicSharedMemorySize, SMEM_SZ);
        attr_set = true;
    }

    fused_kernel<<<grid, NTH, SMEM_SZ>>>(vertices, indices, camera, tables,
                                         W1, B1, W2, B2, W3, B3,
                                         center, scale, (float*)d_out, T);
}